// round 14
// baseline (speedup 1.0000x reference)
#include <cuda_runtime.h>
#include <cuda_fp16.h>
#include <cstdint>

#define NMAX 200000
#define D 128
#define BR 128
#define MAXT 1600
#define DEGI 296

// ---- smem layout per CTA (bytes) ----
#define HA_OFF    0        // hA: 128 x 272
#define RS_OFF    34816    // rS: 128 x 144
#define SLOTS_OFF 53248    // 3 slots x 18432 (Wc spans slots 1..2)
#define SL_SZ     18432
#define BB_OFF    108544
#define LNG_OFF   109056
#define LNB_OFF   109568
#define BB2_OFF   110080
#define LNG2_OFF  110592
#define LNB2_OFF  111104
#define ITEM_OFF  111616
#define SCR_OFF   111632   // 3584: red@+0(2048), zred@+2048(1024); s0: Win@+0, bin@+1536, xS@+2048
static const int SMEM_BYTES = 115216;

__device__ __half g_hh[(size_t)NMAX * D];
__device__ float g_z[NMAX];
__device__ float g_deg[NMAX];
__device__ float g_dis[NMAX];
__device__ float g_u[NMAX];
__device__ float g_t[NMAX];
__device__ __half g_wh[1622016];  // [W1 3x262144 | W2 3x262144 | Wc 3x16384]
__device__ float g_bc[384];
__device__ int g_ctr;
__device__ int g_done[3 * MAXT];
#define OW1 0
#define OW2 786432
#define OWC 1572864

// ---------------------------------------------------------------------------
static __device__ __forceinline__ uint32_t smem_u32(const void* p) {
    uint32_t r;
    asm("{ .reg .u64 t; cvta.to.shared.u64 t, %1; cvt.u32.u64 %0, t; }" : "=r"(r) : "l"(p));
    return r;
}
static __device__ __forceinline__ void cp16h(uint32_t dst, const __half* src) {
    asm volatile("cp.async.cg.shared.global [%0], [%1], 16;\n" :: "r"(dst), "l"(src));
}
static __device__ __forceinline__ void cp_commit() { asm volatile("cp.async.commit_group;\n"); }
template <int NPEND>
static __device__ __forceinline__ void cp_wait() { asm volatile("cp.async.wait_group %0;\n" :: "n"(NPEND)); }

static __device__ __forceinline__ void ldsm4(uint32_t* r, uint32_t addr) {
    asm volatile("ldmatrix.sync.aligned.m8n8.x4.shared.b16 {%0,%1,%2,%3}, [%4];"
                 : "=r"(r[0]), "=r"(r[1]), "=r"(r[2]), "=r"(r[3]) : "r"(addr));
}
static __device__ __forceinline__ void mma16816(float* c, const uint32_t* a,
                                                uint32_t b0, uint32_t b1) {
    asm volatile("mma.sync.aligned.m16n8k16.row.col.f32.f16.f16.f32 "
                 "{%0,%1,%2,%3}, {%4,%5,%6,%7}, {%8,%9}, {%0,%1,%2,%3};"
                 : "+f"(c[0]), "+f"(c[1]), "+f"(c[2]), "+f"(c[3])
                 : "r"(a[0]), "r"(a[1]), "r"(a[2]), "r"(a[3]), "r"(b0), "r"(b1));
}

// ---------------------------------------------------------------------------
// Merged prep: cvt W1, cvt W2, Wc=Wo@Wv, bc, deg_init, flag/counter reset.
__global__ void k_prep(const float* __restrict__ W1, const float* __restrict__ W2,
                       const float* __restrict__ Wo, const float* __restrict__ Wv,
                       const float* __restrict__ bv, const float* __restrict__ bo,
                       int N, int degblocks) {
    const int b = blockIdx.x, tid = threadIdx.x;
    if (b < 3072) {
        int i = b * 256 + tid;
        g_wh[OW1 + i] = __float2half_rn(W1[i]);
    } else if (b < 6144) {
        int i = (b - 3072) * 256 + tid;
        g_wh[OW2 + i] = __float2half_rn(W2[i]);
    } else if (b < 6528) {
        if (tid < 128) {
            int idx = b - 6144;
            int l = idx >> 7, o = idx & 127, d = tid;
            const float* wo = Wo + (size_t)(l * 128 + o) * 128;
            const float* wv = Wv + (size_t)l * 128 * 128;
            float s = 0.f;
#pragma unroll 8
            for (int k = 0; k < 128; k++) s += wo[k] * wv[k * 128 + d];
            g_wh[OWC + (size_t)(l * 128 + o) * 128 + d] = __float2half_rn(s);
        }
    } else if (b < 6576) {
        int wid = (b - 6528) * 8 + (tid >> 5);
        int lane = tid & 31;
        int l = wid >> 7;
        const float* wo = Wo + (size_t)wid * 128;
        float s = 0.f;
#pragma unroll
        for (int q = 0; q < 4; q++) s += wo[lane + q * 32] * bv[l * 128 + lane + q * 32];
#pragma unroll
        for (int o = 16; o; o >>= 1) s += __shfl_xor_sync(0xffffffffu, s, o);
        if (lane == 0) g_bc[wid] = s + bo[wid];
    } else if (b < 6576 + degblocks) {
        int n = (b - 6576) * 256 + tid;
        if (n < N) g_deg[n] = 1.0f;
    } else {
        if (tid == 0) g_ctr = 0;
        for (int i = tid; i < 3 * MAXT; i += 256) g_done[i] = 0;
    }
}

// ---------------------------------------------------------------------------
// Persistent mega, 2 CTAs/SM: 3 (attn+FFN) stages x ntiles + deg items.
__global__ __launch_bounds__(256, 2)
void mega(const float* __restrict__ x, const float* __restrict__ Win,
          const float* __restrict__ b_in,
          const float* __restrict__ b1, const float* __restrict__ b2,
          const float* __restrict__ ln1g, const float* __restrict__ ln1b,
          const float* __restrict__ ln2g, const float* __restrict__ ln2b,
          const float* __restrict__ Wd, const float* __restrict__ bd,
          const int* __restrict__ colE, int E, int N, int ntiles) {
    extern __shared__ __align__(256) unsigned char smem[];
    const int tid = threadIdx.x, w = tid >> 5, lane = tid & 31;
    const int wr = w >> 1, wc = w & 1, r0 = wr * 32;
    const uint32_t sb = smem_u32(smem);
    const int NT3 = 3 * ntiles;

    float* bbS   = (float*)(smem + BB_OFF);
    float* lngS  = (float*)(smem + LNG_OFF);
    float* lnbS  = (float*)(smem + LNB_OFF);
    float* bb2S  = (float*)(smem + BB2_OFF);
    float* lng2S = (float*)(smem + LNG2_OFF);
    float* lnb2S = (float*)(smem + LNB2_OFF);
    float2* red  = (float2*)(smem + SCR_OFF);
    float* zred  = (float*)(smem + SCR_OFF + 2048);
    int* shitem  = (int*)(smem + ITEM_OFF);

    const uint32_t loff272 = (lane & 15) * 272 + (lane >> 4) * 16;
    const uint32_t loff144 = (lane & 15) * 144 + (lane >> 4) * 16;
    const uint32_t haA = sb + HA_OFF + r0 * 272 + loff272;

    for (;;) {
        if (tid == 0) *shitem = atomicAdd(&g_ctr, 1);
        __syncthreads();
        const int item = *shitem;
        __syncthreads();   // everyone read shitem before it can be reused
        if (item >= NT3 + DEGI) return;
        if (item >= NT3) {                           // degree count (independent)
            int di = item - NT3;
            int slice = (E + DEGI - 1) / DEGI;
            int e0 = di * slice, e1 = min(e0 + slice, E);
            for (int e = e0 + tid; e < e1; e += 256)
                atomicAdd(&g_deg[colE[e]], 1.0f);
            continue;
        }

        const int s = item / ntiles;
        const int t = item - s * ntiles;
        const int row0 = t * BR;

        const __half* Wc = g_wh + OWC + (size_t)s * 16384;
        const __half* Wa = g_wh + OW1 + (size_t)s * 262144;
        const __half* Wb = g_wh + OW2 + (size_t)s * 262144;
        const float* b1s = b1 + s * 2048;

        if (s > 0 && tid == 0) {
            while (atomicAdd(&g_done[(s - 1) * ntiles + t], 0) == 0) __nanosleep(64);
            __threadfence();
        }
        __syncthreads();

        // G_a (s>0): hA via cp.async from fp16 g_hh
        if (s > 0) {
            const __half* hsrc = g_hh + (size_t)row0 * D;
            for (int i = tid; i < BR * 16; i += 256) {
                int r = i >> 4, q = i & 15;
                if (row0 + r < N)
                    cp16h(sb + HA_OFF + r * 272 + q * 16, hsrc + (size_t)r * 128 + q * 8);
                else
                    *(uint4*)(smem + HA_OFF + r * 272 + q * 16) = make_uint4(0, 0, 0, 0);
            }
            cp_commit();
        }
        // G_b: Wc -> slots 1..2 (contiguous, stride 272)
        for (int i = tid; i < 2048; i += 256) {
            int r = i >> 4, q = i & 15;
            cp16h(sb + SLOTS_OFF + SL_SZ + r * 272 + q * 16, Wc + (size_t)r * 128 + q * 8);
        }
        cp_commit();
        // G_c: Wa[0] -> slot 0
        for (int i = tid; i < 1024; i += 256) {
            int r = i >> 4, q = i & 15;
            cp16h(sb + SLOTS_OFF + r * 272 + q * 16, Wa + (size_t)r * 128 + q * 8);
        }
        cp_commit();

        // ---- s==0: compute hA = relu(x @ Win^T + b_in) ----
        if (s == 0) {
            float* WinS = (float*)(smem + SCR_OFF);
            float* binS = (float*)(smem + SCR_OFF + 1536);
            float* xS   = (float*)(smem + SCR_OFF + 2048);
            if (tid < 128) binS[tid] = b_in[tid];
            for (int i = tid; i < 384; i += 256) WinS[i] = Win[i];
            for (int i = tid; i < 384; i += 256) {
                int gi = row0 * 3 + i;
                xS[i] = (gi < N * 3) ? x[gi] : 0.f;
            }
            __syncthreads();
            for (int i = tid; i < BR * 64; i += 256) {
                int r = i >> 6, j = i & 63, c = 2 * j;
                int gr = row0 + r;
                float v0 = 0.f, v1 = 0.f;
                if (gr < N) {
                    float x0 = xS[r * 3], x1 = xS[r * 3 + 1], x2 = xS[r * 3 + 2];
                    v0 = fmaxf(binS[c] + x0 * WinS[c * 3] + x1 * WinS[c * 3 + 1]
                               + x2 * WinS[c * 3 + 2], 0.f);
                    v1 = fmaxf(binS[c + 1] + x0 * WinS[(c + 1) * 3] + x1 * WinS[(c + 1) * 3 + 1]
                               + x2 * WinS[(c + 1) * 3 + 2], 0.f);
                }
                __half2 h2 = __floats2half2_rn(v0, v1);
                *(uint32_t*)(smem + HA_OFF + r * 272 + j * 4) = *(uint32_t*)&h2;
            }
        }
        // per-layer small biases
        if (tid < 128) {
            bbS[tid]   = g_bc[s * 128 + tid];
            lngS[tid]  = ln1g[s * 128 + tid];
            lnbS[tid]  = ln1b[s * 128 + tid];
            bb2S[tid]  = b2[s * 128 + tid];
            lng2S[tid] = ln2g[s * 128 + tid];
            lnb2S[tid] = ln2b[s * 128 + tid];
        }

        cp_wait<1>();     // hA + Wc landed; Wa0 may fly
        __syncthreads();

        float acc[2][8][4];
#pragma unroll
        for (int m = 0; m < 2; m++)
#pragma unroll
            for (int n = 0; n < 8; n++)
#pragma unroll
                for (int e = 0; e < 4; e++) acc[m][n][e] = 0.f;

        // ======== attn GEMM: acc = hA @ Wc^T (Wc in slots 1..2) ========
        {
            const uint32_t bB = sb + SLOTS_OFF + SL_SZ + (wc * 64) * 272 + loff272;
            uint32_t a[2][4], b[4][4];
#pragma unroll
            for (int kk = 0; kk < 8; kk++) {
                ldsm4(a[0], haA + kk * 32);
                ldsm4(a[1], haA + 16 * 272 + kk * 32);
#pragma unroll
                for (int g = 0; g < 4; g++) ldsm4(b[g], bB + g * 16 * 272 + kk * 32);
#pragma unroll
                for (int m = 0; m < 2; m++)
#pragma unroll
                    for (int n = 0; n < 8; n++)
                        mma16816(acc[m][n], a[m], b[n >> 1][n & 1], b[n >> 1][(n & 1) + 2]);
            }
        }

        // ======== attn epilogue: LN1 -> hA (fp16) ========
#pragma unroll
        for (int m = 0; m < 2; m++)
#pragma unroll
            for (int h = 0; h < 2; h++) {
                int lr = r0 + m * 16 + (lane >> 2) + h * 8;
                int gr = row0 + lr;
                float ss = 0.f, qq = 0.f;
                if (gr < N) {
#pragma unroll
                    for (int n = 0; n < 8; n++) {
                        int c = wc * 64 + n * 8 + (lane & 3) * 2;
                        __half2 hh = *(__half2*)(smem + HA_OFF + lr * 272 + c * 2);
                        float2 ho = __half22float2(hh);
                        float v0 = acc[m][n][h * 2 + 0] + ho.x + bbS[c];
                        float v1 = acc[m][n][h * 2 + 1] + ho.y + bbS[c + 1];
                        ss += v0 + v1;
                        qq += v0 * v0 + v1 * v1;
                    }
                }
                ss += __shfl_xor_sync(0xffffffffu, ss, 1);
                ss += __shfl_xor_sync(0xffffffffu, ss, 2);
                qq += __shfl_xor_sync(0xffffffffu, qq, 1);
                qq += __shfl_xor_sync(0xffffffffu, qq, 2);
                if ((lane & 3) == 0) red[lr * 2 + wc] = make_float2(ss, qq);
            }
        asm volatile("bar.sync %0, 64;" :: "r"(1 + wr) : "memory");
#pragma unroll
        for (int m = 0; m < 2; m++)
#pragma unroll
            for (int h = 0; h < 2; h++) {
                int lr = r0 + m * 16 + (lane >> 2) + h * 8;
                int gr = row0 + lr;
                if (gr >= N) continue;
                float2 p0 = red[lr * 2 + 0], p1 = red[lr * 2 + 1];
                float mean = (p0.x + p1.x) * (1.f / 128.f);
                float inv = rsqrtf((p0.y + p1.y) * (1.f / 128.f) - mean * mean + 1e-5f);
#pragma unroll
                for (int n = 0; n < 8; n++) {
                    int c = wc * 64 + n * 8 + (lane & 3) * 2;
                    __half2 hh = *(__half2*)(smem + HA_OFF + lr * 272 + c * 2);
                    float2 ho = __half22float2(hh);
                    float v0 = acc[m][n][h * 2 + 0] + ho.x + bbS[c];
                    float v1 = acc[m][n][h * 2 + 1] + ho.y + bbS[c + 1];
                    float o0 = (v0 - mean) * inv * lngS[c] + lnbS[c];
                    float o1 = (v1 - mean) * inv * lngS[c + 1] + lnbS[c + 1];
                    __half2 oo = __floats2half2_rn(o0, o1);
                    *(uint32_t*)(smem + HA_OFF + lr * 272 + c * 2) = *(uint32_t*)&oo;
                }
            }
        __syncthreads();  // Wc reads + hA updates done everywhere

        // G_d: Wb[0] -> slot 1 (frees after attn)
        for (int i = tid; i < 1024; i += 256) {
            int r = i >> 3, q = i & 7;
            cp16h(sb + SLOTS_OFF + SL_SZ + r * 144 + q * 16, Wb + (size_t)r * 2048 + q * 8);
        }
        cp_commit();

#pragma unroll
        for (int m = 0; m < 2; m++)
#pragma unroll
            for (int n = 0; n < 8; n++)
#pragma unroll
                for (int e = 0; e < 4; e++) acc[m][n][e] = 0.f;

        // ======== FFN: 32 chunks; ring-of-3 slots ========
        for (int ch = 0; ch < 32; ch++) {
            const int f0 = ch << 6;
            const int sa = (2 * ch) % 3;
            const int sbx = (2 * ch + 1) % 3;
            const uint32_t sWa = sb + SLOTS_OFF + sa * SL_SZ;
            const uint32_t sWb = sb + SLOTS_OFF + sbx * SL_SZ;

            cp_wait<0>();
            __syncthreads();   // Wa[ch],Wb[ch] visible; stage2(ch-1) reads done

            // bias prefetch (registers, L2)
            float2 biasr[4];
#pragma unroll
            for (int n = 0; n < 4; n++) {
                int c = wc * 32 + n * 8 + (lane & 3) * 2;
                biasr[n] = __ldg((const float2*)(b1s + f0 + c));
            }

            if (ch + 1 < 32) {   // Wa[ch+1] -> slot (2ch+2)%3 (= Wb[ch-1]'s, free)
                uint32_t nWa = sb + SLOTS_OFF + ((2 * ch + 2) % 3) * SL_SZ;
                const __half* srcA = Wa + (size_t)(f0 + 64) * 128;
                for (int i = tid; i < 1024; i += 256) {
                    int r = i >> 4, q = i & 15;
                    cp16h(nWa + r * 272 + q * 16, srcA + (size_t)r * 128 + q * 8);
                }
                cp_commit();
            }

            // stage 1
            float rf[2][4][4];
#pragma unroll
            for (int m = 0; m < 2; m++)
#pragma unroll
                for (int n = 0; n < 4; n++)
#pragma unroll
                    for (int e = 0; e < 4; e++) rf[m][n][e] = 0.f;
            {
                const uint32_t bB = sWa + (wc * 32) * 272 + loff272;
                uint32_t a[2][4], b[2][4];
#pragma unroll
                for (int kk = 0; kk < 8; kk++) {
                    ldsm4(a[0], haA + kk * 32);
                    ldsm4(a[1], haA + 16 * 272 + kk * 32);
                    ldsm4(b[0], bB + kk * 32);
                    ldsm4(b[1], bB + 16 * 272 + kk * 32);
#pragma unroll
                    for (int m = 0; m < 2; m++)
#pragma unroll
                        for (int n = 0; n < 4; n++)
                            mma16816(rf[m][n], a[m], b[n >> 1][n & 1], b[n >> 1][(n & 1) + 2]);
                }
            }
            // mid: bias + relu + pack; keep own-half fragments in regs
            uint32_t pk[2][4][2];
#pragma unroll
            for (int m = 0; m < 2; m++)
#pragma unroll
                for (int n = 0; n < 4; n++) {
                    int c = wc * 32 + n * 8 + (lane & 3) * 2;
                    int rowb = r0 + m * 16 + (lane >> 2);
                    __half2 p0 = __floats2half2_rn(fmaxf(rf[m][n][0] + biasr[n].x, 0.f),
                                                   fmaxf(rf[m][n][1] + biasr[n].y, 0.f));
                    pk[m][n][0] = *(uint32_t*)&p0;
                    *(uint32_t*)(smem + RS_OFF + rowb * 144 + c * 2) = pk[m][n][0];
                    __half2 p1 = __floats2half2_rn(fmaxf(rf[m][n][2] + biasr[n].x, 0.f),
                                                   fmaxf(rf[m][n][3] + biasr[n].y, 0.f));
                    pk[m][n][1] = *(uint32_t*)&p1;
                    *(uint32_t*)(smem + RS_OFF + (rowb + 8) * 144 + c * 2) = pk[m][n][1];
                }
            __syncthreads();   // rS ready; Wa[ch] slot reads done

            if (ch + 1 < 32) {   // Wb[ch+1] -> slot (2ch)%3 (= Wa[ch]'s, now free)
                uint32_t nWb = sb + SLOTS_OFF + sa * SL_SZ;
                const __half* srcB = Wb + (f0 + 64);
                for (int i = tid; i < 1024; i += 256) {
                    int r = i >> 3, q = i & 7;
                    cp16h(nWb + r * 144 + q * 16, srcB + (size_t)r * 2048 + q * 8);
                }
                cp_commit();
            }

            // stage 2: own k-half A from registers, partner half from rS
            {
                const uint32_t aB = sb + RS_OFF + r0 * 144 + loff144;
                const uint32_t bB = sWb + (wc * 64) * 144 + loff144;
                uint32_t a[2][4], b[4][4];
#pragma unroll
                for (int kk = 0; kk < 4; kk++) {
                    if ((kk >> 1) == wc) {
                        int j = kk & 1;
#pragma unroll
                        for (int m = 0; m < 2; m++) {
                            a[m][0] = pk[m][2 * j][0];
                            a[m][1] = pk[m][2 * j][1];
                            a[m][2] = pk[m][2 * j + 1][0];
                            a[m][3] = pk[m][2 * j + 1][1];
                        }
                    } else {
                        ldsm4(a[0], aB + kk * 32);
                        ldsm4(a[1], aB + 16 * 144 + kk * 32);
                    }
#pragma unroll
                    for (int g = 0; g < 4; g++) ldsm4(b[g], bB + g * 16 * 144 + kk * 32);
#pragma unroll
                    for (int m = 0; m < 2; m++)
#pragma unroll
                        for (int n = 0; n < 8; n++)
                            mma16816(acc[m][n], a[m], b[n >> 1][n & 1], b[n >> 1][(n & 1) + 2]);
                }
            }
        }

        // ======== FFN epilogue: LN2 -> g_hh (s<2) / z-head (s==2) ========
#pragma unroll
        for (int m = 0; m < 2; m++)
#pragma unroll
            for (int h = 0; h < 2; h++) {
                int lr = r0 + m * 16 + (lane >> 2) + h * 8;
                int gr = row0 + lr;
                float ss = 0.f, qq = 0.f;
                if (gr < N) {
#pragma unroll
                    for (int n = 0; n < 8; n++) {
                        int c = wc * 64 + n * 8 + (lane & 3) * 2;
                        __half2 hh = *(__half2*)(smem + HA_OFF + lr * 272 + c * 2);
                        float2 ho = __half22float2(hh);
                        float v0 = acc[m][n][h * 2 + 0] + ho.x + bb2S[c];
                        float v1 = acc[m][n][h * 2 + 1] + ho.y + bb2S[c + 1];
                        ss += v0 + v1;
                        qq += v0 * v0 + v1 * v1;
                    }
                }
                ss += __shfl_xor_sync(0xffffffffu, ss, 1);
                ss += __shfl_xor_sync(0xffffffffu, ss, 2);
                qq += __shfl_xor_sync(0xffffffffu, qq, 1);
                qq += __shfl_xor_sync(0xffffffffu, qq, 2);
                if ((lane & 3) == 0) red[lr * 2 + wc] = make_float2(ss, qq);
            }
        asm volatile("bar.sync %0, 64;" :: "r"(1 + wr) : "memory");
#pragma unroll
        for (int m = 0; m < 2; m++)
#pragma unroll
            for (int h = 0; h < 2; h++) {
                int lr = r0 + m * 16 + (lane >> 2) + h * 8;
                int gr = row0 + lr;
                float zp = 0.f;
                if (gr < N) {
                    float2 p0 = red[lr * 2 + 0], p1 = red[lr * 2 + 1];
                    float mean = (p0.x + p1.x) * (1.f / 128.f);
                    float inv = rsqrtf((p0.y + p1.y) * (1.f / 128.f) - mean * mean + 1e-5f);
#pragma unroll
                    for (int n = 0; n < 8; n++) {
                        int c = wc * 64 + n * 8 + (lane & 3) * 2;
                        __half2 hh = *(__half2*)(smem + HA_OFF + lr * 272 + c * 2);
                        float2 ho = __half22float2(hh);
                        float v0 = acc[m][n][h * 2 + 0] + ho.x + bb2S[c];
                        float v1 = acc[m][n][h * 2 + 1] + ho.y + bb2S[c + 1];
                        float o0 = (v0 - mean) * inv * lng2S[c] + lnb2S[c];
                        float o1 = (v1 - mean) * inv * lng2S[c + 1] + lnb2S[c + 1];
                        if (s != 2) {
                            *(__half2*)(g_hh + (size_t)gr * D + c) = __floats2half2_rn(o0, o1);
                        } else {
                            float2 wd = __ldg((const float2*)(Wd + c));
                            zp += o0 * wd.x + o1 * wd.y;
                        }
                    }
                }
                if (s == 2) {
                    zp += __shfl_xor_sync(0xffffffffu, zp, 1);
                    zp += __shfl_xor_sync(0xffffffffu, zp, 2);
                    if ((lane & 3) == 0) zred[lr * 2 + wc] = zp;
                }
            }
        if (s == 2) {
            asm volatile("bar.sync %0, 64;" :: "r"(1 + wr) : "memory");
            float bdv = __ldg(bd);
#pragma unroll
            for (int m = 0; m < 2; m++)
#pragma unroll
                for (int h = 0; h < 2; h++) {
                    int lr = r0 + m * 16 + (lane >> 2) + h * 8;
                    int gr = row0 + lr;
                    if (gr < N && (lane & 3) == 0 && wc == 0)
                        g_z[gr] = fmaxf(zred[lr * 2] + zred[lr * 2 + 1] + bdv, 0.f);
                }
        }

        __threadfence();
        __syncthreads();
        if (tid == 0 && s < 2) atomicExch(&g_done[s * ntiles + t], 1);
    }
}

// ---------------------------------------------------------------------------
__global__ void k_dis_u(int N) {
    int n = blockIdx.x * blockDim.x + threadIdx.x;
    if (n >= N) return;
    float dis = rsqrtf(fmaxf(g_deg[n], 1.0f));
    float u = g_z[n] * dis;
    g_dis[n] = dis;
    g_u[n] = u;
    g_t[n] = u;
}
__global__ void k_scatter(const int* __restrict__ row, const int* __restrict__ col, int E) {
    int e = blockIdx.x * blockDim.x + threadIdx.x;
    if (e < E) atomicAdd(&g_t[col[e]], g_u[row[e]]);
}
__global__ void k_out(const float* __restrict__ Wg, const float* __restrict__ bg,
                      const float* __restrict__ Wf, const float* __restrict__ bf,
                      float* __restrict__ out, int N) {
    int n = blockIdx.x * blockDim.x + threadIdx.x;
    if (n >= N) return;
    float s = g_dis[n] * g_t[n];
    float a = bf[0];
#pragma unroll
    for (int k = 0; k < 32; k++)
        a += fmaxf(s * Wg[k] + bg[k], 0.f) * Wf[k];
    out[n] = a;
}

// ---------------------------------------------------------------------------
extern "C" void kernel_launch(void* const* d_in, const int* in_sizes, int n_in,
                              void* d_out, int out_size) {
    const float* x    = (const float*)d_in[0];
    const int*   edge = (const int*)  d_in[1];
    const float* Win  = (const float*)d_in[2];
    const float* b_in = (const float*)d_in[3];
    const float* Wv   = (const float*)d_in[4];
    const float* bv   = (const float*)d_in[5];
    const float* Wo   = (const float*)d_in[6];
    const float* bo   = (const float*)d_in[7];
    const float* W1   = (const float*)d_in[8];
    const float* b1   = (const float*)d_in[9];
    const float* W2   = (const float*)d_in[10];
    const float* b2   = (const float*)d_in[11];
    const float* ln1g = (const float*)d_in[12];
    const float* ln1b = (const float*)d_in[13];
    const float* ln2g = (const float*)d_in[14];
    const float* ln2b = (const float*)d_in[15];
    const float* Wd   = (const float*)d_in[16];
    const float* bd   = (const float*)d_in[17];
    const float* Wg   = (const float*)d_in[18];
    const float* bg   = (const float*)d_in[19];
    const float* Wf   = (const float*)d_in[20];
    const float* bf   = (const float*)d_in[21];

    const int N = in_sizes[0] / 3;
    const int E = in_sizes[1] / 2;
    const int ntiles = (N + BR - 1) / BR;
    const int degblocks = (N + 255) / 256;

    int sms = 148;
    cudaDeviceGetAttribute(&sms, cudaDevAttrMultiProcessorCount, 0);

    cudaFuncSetAttribute(mega, cudaFuncAttributeMaxDynamicSharedMemorySize, SMEM_BYTES);

    k_prep<<<6576 + degblocks + 1, 256>>>(W1, W2, Wo, Wv, bv, bo, N, degblocks);

    mega<<<2 * sms, 256, SMEM_BYTES>>>(x, Win, b_in, b1, b2, ln1g, ln1b, ln2g, ln2b,
                                       Wd, bd, edge + E, E, N, ntiles);

    k_dis_u<<<(N + 255) / 256, 256>>>(N);
    k_scatter<<<(E + 255) / 256, 256>>>(edge, edge + E, E);
    k_out<<<(N + 255) / 256, 256>>>(Wg, bg, Wf, bf, (float*)d_out, N);
}

// round 16
// speedup vs baseline: 1.0347x; 1.0347x over previous
#include <cuda_runtime.h>
#include <cuda_fp16.h>
#include <cstdint>

#define NMAX 200000
#define D 128
#define BR 256
#define MAXT 800
#define DEGI 296

// ---- smem layout (bytes) ----
#define HA_OFF   0         // hA: 256 x 272                    69632
#define RS0_OFF  69632     // rS sub0: 256 x 144               36864
#define RS1_OFF  106496    // rS sub1: 256 x 144               36864
#define SA_OFF   143360    // Wa slot: 128 x 272               34816
#define SB_OFF   178176    // Wb slots: 2 x (128 x 144)        36864
#define BB_OFF   215040
#define LNG_OFF  215552
#define LNB_OFF  216064
#define BB2_OFF  216576
#define LNG2_OFF 217088
#define LNB2_OFF 217600
#define RED_OFF  218112    // float2[256][2] = 4096 ; s0: Win(1536)+bin(512)
#define ZRED_OFF 222208    // float[256][2] = 2048
#define WD_OFF   224256    // 129 floats (516 B)
#define ITEM_OFF 224776
static const int SMEM_BYTES = 224792;

__device__ __half g_hh[(size_t)NMAX * D];
__device__ float g_z[NMAX];
__device__ float g_deg[NMAX];
__device__ float g_dis[NMAX];
__device__ float g_u[NMAX];
__device__ float g_t[NMAX];
__device__ __half g_wh[1622016];  // [W1 3x262144 | W2 3x262144 | Wc 3x16384]
__device__ float g_bc[384];
__device__ int g_ctr;
__device__ int g_done[3 * MAXT];
#define OW1 0
#define OW2 786432
#define OWC 1572864

// ---------------------------------------------------------------------------
static __device__ __forceinline__ uint32_t smem_u32(const void* p) {
    uint32_t r;
    asm("{ .reg .u64 t; cvta.to.shared.u64 t, %1; cvt.u32.u64 %0, t; }" : "=r"(r) : "l"(p));
    return r;
}
static __device__ __forceinline__ void cp16h(uint32_t dst, const __half* src) {
    asm volatile("cp.async.cg.shared.global [%0], [%1], 16;\n" :: "r"(dst), "l"(src));
}
static __device__ __forceinline__ void cp_commit() { asm volatile("cp.async.commit_group;\n"); }
template <int NPEND>
static __device__ __forceinline__ void cp_wait() { asm volatile("cp.async.wait_group %0;\n" :: "n"(NPEND)); }

static __device__ __forceinline__ void ldsm4(uint32_t* r, uint32_t addr) {
    asm volatile("ldmatrix.sync.aligned.m8n8.x4.shared.b16 {%0,%1,%2,%3}, [%4];"
                 : "=r"(r[0]), "=r"(r[1]), "=r"(r[2]), "=r"(r[3]) : "r"(addr));
}
static __device__ __forceinline__ void mma16816(float* c, const uint32_t* a,
                                                uint32_t b0, uint32_t b1) {
    asm volatile("mma.sync.aligned.m16n8k16.row.col.f32.f16.f16.f32 "
                 "{%0,%1,%2,%3}, {%4,%5,%6,%7}, {%8,%9}, {%0,%1,%2,%3};"
                 : "+f"(c[0]), "+f"(c[1]), "+f"(c[2]), "+f"(c[3])
                 : "r"(a[0]), "r"(a[1]), "r"(a[2]), "r"(a[3]), "r"(b0), "r"(b1));
}

// ---------------------------------------------------------------------------
// Merged prep: cvt W1, cvt W2, Wc=Wo@Wv, bc, deg_init, flag/counter reset.
__global__ void k_prep(const float* __restrict__ W1, const float* __restrict__ W2,
                       const float* __restrict__ Wo, const float* __restrict__ Wv,
                       const float* __restrict__ bv, const float* __restrict__ bo,
                       int N, int degblocks) {
    const int b = blockIdx.x, tid = threadIdx.x;
    if (b < 3072) {
        int i = b * 256 + tid;
        g_wh[OW1 + i] = __float2half_rn(W1[i]);
    } else if (b < 6144) {
        int i = (b - 3072) * 256 + tid;
        g_wh[OW2 + i] = __float2half_rn(W2[i]);
    } else if (b < 6528) {
        if (tid < 128) {
            int idx = b - 6144;
            int l = idx >> 7, o = idx & 127, d = tid;
            const float* wo = Wo + (size_t)(l * 128 + o) * 128;
            const float* wv = Wv + (size_t)l * 128 * 128;
            float s = 0.f;
#pragma unroll 8
            for (int k = 0; k < 128; k++) s += wo[k] * wv[k * 128 + d];
            g_wh[OWC + (size_t)(l * 128 + o) * 128 + d] = __float2half_rn(s);
        }
    } else if (b < 6576) {
        int wid = (b - 6528) * 8 + (tid >> 5);
        int lane = tid & 31;
        int l = wid >> 7;
        const float* wo = Wo + (size_t)wid * 128;
        float s = 0.f;
#pragma unroll
        for (int q = 0; q < 4; q++) s += wo[lane + q * 32] * bv[l * 128 + lane + q * 32];
#pragma unroll
        for (int o = 16; o; o >>= 1) s += __shfl_xor_sync(0xffffffffu, s, o);
        if (lane == 0) g_bc[wid] = s + bo[wid];
    } else if (b < 6576 + degblocks) {
        int n = (b - 6576) * 256 + tid;
        if (n < N) g_deg[n] = 1.0f;
    } else {
        if (tid == 0) g_ctr = 0;
        for (int i = tid; i < 3 * MAXT; i += 256) g_done[i] = 0;
    }
}

// ---------------------------------------------------------------------------
// Persistent mega: 3 (attn+FFN) stages x ntiles + independent deg items.
// FFN: 16 iters x 128 f (2 sub-chunks); 2 block syncs per iter.
__global__ __launch_bounds__(512, 1)
void mega(const float* __restrict__ x, const float* __restrict__ Win,
          const float* __restrict__ b_in,
          const float* __restrict__ b1, const float* __restrict__ b2,
          const float* __restrict__ ln1g, const float* __restrict__ ln1b,
          const float* __restrict__ ln2g, const float* __restrict__ ln2b,
          const float* __restrict__ Wd, const float* __restrict__ bd,
          const int* __restrict__ colE, int E, int N, int ntiles) {
    extern __shared__ __align__(256) unsigned char smem[];
    const int tid = threadIdx.x, w = tid >> 5, lane = tid & 31;
    const int wr = w >> 1, wc = w & 1, r0 = wr * 32;
    const uint32_t sb = smem_u32(smem);
    const int NT3 = 3 * ntiles;

    float* bbS   = (float*)(smem + BB_OFF);
    float* lngS  = (float*)(smem + LNG_OFF);
    float* lnbS  = (float*)(smem + LNB_OFF);
    float* bb2S  = (float*)(smem + BB2_OFF);
    float* lng2S = (float*)(smem + LNG2_OFF);
    float* lnb2S = (float*)(smem + LNB2_OFF);
    float2* red  = (float2*)(smem + RED_OFF);
    float* zred  = (float*)(smem + ZRED_OFF);
    float* WdS   = (float*)(smem + WD_OFF);
    int* shitem  = (int*)(smem + ITEM_OFF);

    const uint32_t loff272 = (lane & 15) * 272 + (lane >> 4) * 16;
    const uint32_t loff144 = (lane & 15) * 144 + (lane >> 4) * 16;
    const uint32_t haA = sb + HA_OFF + r0 * 272 + loff272;

    for (;;) {
        if (tid == 0) *shitem = atomicAdd(&g_ctr, 1);
        __syncthreads();
        const int item = *shitem;
        if (item >= NT3 + DEGI) return;
        if (item >= NT3) {                           // degree count (independent)
            int di = item - NT3;
            int slice = (E + DEGI - 1) / DEGI;
            int e0 = di * slice, e1 = min(e0 + slice, E);
            for (int e = e0 + tid; e < e1; e += 512)
                atomicAdd(&g_deg[colE[e]], 1.0f);
            __syncthreads();
            continue;
        }

        const int s = item / ntiles;
        const int t = item - s * ntiles;
        const int row0 = t * BR;

        const __half* Wc = g_wh + OWC + (size_t)s * 16384;
        const __half* Wa = g_wh + OW1 + (size_t)s * 262144;
        const __half* Wb = g_wh + OW2 + (size_t)s * 262144;
        const float* b1s = b1 + s * 2048;

        if (s > 0 && tid == 0) {
            while (atomicAdd(&g_done[(s - 1) * ntiles + t], 0) == 0) __nanosleep(64);
            __threadfence();
        }
        __syncthreads();

        // G_hA (s>0): via cp.async from fp16 g_hh
        if (s > 0) {
            const __half* hsrc = g_hh + (size_t)row0 * D;
            for (int i = tid; i < BR * 16; i += 512) {
                int r = i >> 4, q = i & 15;
                if (row0 + r < N)
                    cp16h(sb + HA_OFF + r * 272 + q * 16, hsrc + (size_t)r * 128 + q * 8);
                else
                    *(uint4*)(smem + HA_OFF + r * 272 + q * 16) = make_uint4(0, 0, 0, 0);
            }
        }
        // G_Wc -> SA (128 rows x 272)
        for (int i = tid; i < 2048; i += 512) {
            int r = i >> 4, q = i & 15;
            cp16h(sb + SA_OFF + r * 272 + q * 16, Wc + (size_t)r * 128 + q * 8);
        }
        cp_commit();

        // ---- s==0: compute hA = relu(x @ Win^T + b_in) ----
        if (s == 0) {
            float* WinS = (float*)(smem + RED_OFF);
            float* binS = (float*)(smem + RED_OFF + 1536);
            float* xS   = (float*)(smem + RS0_OFF);   // rS free at this point
            if (tid < 384) WinS[tid] = Win[tid];
            else if (tid < 512) binS[tid - 384] = b_in[tid - 384];
            for (int i = tid; i < 768; i += 512) {
                int gi = row0 * 3 + i;
                xS[i] = (gi < N * 3) ? x[gi] : 0.f;
            }
            __syncthreads();
            for (int i = tid; i < BR * 64; i += 512) {
                int r = i >> 6, j = i & 63, c = 2 * j;
                int gr = row0 + r;
                float v0 = 0.f, v1 = 0.f;
                if (gr < N) {
                    float x0 = xS[r * 3], x1 = xS[r * 3 + 1], x2 = xS[r * 3 + 2];
                    v0 = fmaxf(binS[c] + x0 * WinS[c * 3] + x1 * WinS[c * 3 + 1]
                               + x2 * WinS[c * 3 + 2], 0.f);
                    v1 = fmaxf(binS[c + 1] + x0 * WinS[(c + 1) * 3] + x1 * WinS[(c + 1) * 3 + 1]
                               + x2 * WinS[(c + 1) * 3 + 2], 0.f);
                }
                __half2 h2 = __floats2half2_rn(v0, v1);
                *(uint32_t*)(smem + HA_OFF + r * 272 + j * 4) = *(uint32_t*)&h2;
            }
        }
        // biases
        if (tid < 128) {
            bbS[tid]   = g_bc[s * 128 + tid];
            lngS[tid]  = ln1g[s * 128 + tid];
            lnbS[tid]  = ln1b[s * 128 + tid];
            bb2S[tid]  = b2[s * 128 + tid];
            lng2S[tid] = ln2g[s * 128 + tid];
            lnb2S[tid] = ln2b[s * 128 + tid];
        }
        if (s == 2) {
            if (tid < 128) WdS[tid] = Wd[tid];
            if (tid == 128) WdS[128] = bd[0];
        }

        cp_wait<0>();
        __syncthreads();   // hA + Wc visible; biases visible

        float acc[2][8][4];
#pragma unroll
        for (int m = 0; m < 2; m++)
#pragma unroll
            for (int n = 0; n < 8; n++)
#pragma unroll
                for (int e = 0; e < 4; e++) acc[m][n][e] = 0.f;

        // ======== attn GEMM: acc = hA @ Wc^T (Wc in SA) ========
        {
            const uint32_t bB = sb + SA_OFF + (wc * 64) * 272 + loff272;
            uint32_t a[2][4], b[4][4];
#pragma unroll
            for (int kk = 0; kk < 8; kk++) {
                ldsm4(a[0], haA + kk * 32);
                ldsm4(a[1], haA + 16 * 272 + kk * 32);
#pragma unroll
                for (int g = 0; g < 4; g++) ldsm4(b[g], bB + g * 16 * 272 + kk * 32);
#pragma unroll
                for (int m = 0; m < 2; m++)
#pragma unroll
                    for (int n = 0; n < 8; n++)
                        mma16816(acc[m][n], a[m], b[n >> 1][n & 1], b[n >> 1][(n & 1) + 2]);
            }
        }

        // ======== attn epilogue: LN1 -> hA (fp16) ========
#pragma unroll
        for (int m = 0; m < 2; m++)
#pragma unroll
            for (int h = 0; h < 2; h++) {
                int lr = r0 + m * 16 + (lane >> 2) + h * 8;
                int gr = row0 + lr;
                float ss = 0.f, qq = 0.f;
                if (gr < N) {
#pragma unroll
                    for (int n = 0; n < 8; n++) {
                        int c = wc * 64 + n * 8 + (lane & 3) * 2;
                        __half2 hh = *(__half2*)(smem + HA_OFF + lr * 272 + c * 2);
                        float2 ho = __half22float2(hh);
                        float v0 = acc[m][n][h * 2 + 0] + ho.x + bbS[c];
                        float v1 = acc[m][n][h * 2 + 1] + ho.y + bbS[c + 1];
                        ss += v0 + v1;
                        qq += v0 * v0 + v1 * v1;
                    }
                }
                ss += __shfl_xor_sync(0xffffffffu, ss, 1);
                ss += __shfl_xor_sync(0xffffffffu, ss, 2);
                qq += __shfl_xor_sync(0xffffffffu, qq, 1);
                qq += __shfl_xor_sync(0xffffffffu, qq, 2);
                if ((lane & 3) == 0) red[lr * 2 + wc] = make_float2(ss, qq);
            }
        asm volatile("bar.sync %0, 64;" :: "r"(1 + wr) : "memory");
#pragma unroll
        for (int m = 0; m < 2; m++)
#pragma unroll
            for (int h = 0; h < 2; h++) {
                int lr = r0 + m * 16 + (lane >> 2) + h * 8;
                int gr = row0 + lr;
                if (gr >= N) continue;
                float2 p0 = red[lr * 2 + 0], p1 = red[lr * 2 + 1];
                float mean = (p0.x + p1.x) * (1.f / 128.f);
                float inv = rsqrtf((p0.y + p1.y) * (1.f / 128.f) - mean * mean + 1e-5f);
#pragma unroll
                for (int n = 0; n < 8; n++) {
                    int c = wc * 64 + n * 8 + (lane & 3) * 2;
                    __half2 hh = *(__half2*)(smem + HA_OFF + lr * 272 + c * 2);
                    float2 ho = __half22float2(hh);
                    float v0 = acc[m][n][h * 2 + 0] + ho.x + bbS[c];
                    float v1 = acc[m][n][h * 2 + 1] + ho.y + bbS[c + 1];
                    float o0 = (v0 - mean) * inv * lngS[c] + lnbS[c];
                    float o1 = (v1 - mean) * inv * lngS[c + 1] + lnbS[c + 1];
                    __half2 oo = __floats2half2_rn(o0, o1);
                    *(uint32_t*)(smem + HA_OFF + lr * 272 + c * 2) = *(uint32_t*)&oo;
                }
            }
        __syncthreads();   // SA reads (attn) + hA updates done

        // G_Wa(0) -> SA (128 rows of Wa)
        for (int i = tid; i < 2048; i += 512) {
            int r = i >> 4, q = i & 15;
            cp16h(sb + SA_OFF + r * 272 + q * 16, Wa + (size_t)r * 128 + q * 8);
        }
        cp_commit();

#pragma unroll
        for (int m = 0; m < 2; m++)
#pragma unroll
            for (int n = 0; n < 8; n++)
#pragma unroll
                for (int e = 0; e < 4; e++) acc[m][n][e] = 0.f;

        // ======== FFN: 16 iters x 128 f ========
        for (int it = 0; it < 16; it++) {
            const int f0 = it << 7;

            cp_wait<0>();
            __syncthreads();   // Wa(it) visible; prev stage2 done (SB, rS free)

            // issue Wb(it) -> SB (128 d rows x 128 f cols, split by sub)
            for (int i = tid; i < 2048; i += 512) {
                int sub = i >> 10, r = (i >> 3) & 127, q = i & 7;
                cp16h(sb + SB_OFF + sub * 18432 + r * 144 + q * 16,
                      Wb + (size_t)r * 2048 + f0 + sub * 64 + q * 8);
            }
            cp_commit();

            // stage 1, sub 0 and 1
#pragma unroll
            for (int sub = 0; sub < 2; sub++) {
                const int fsub = f0 + sub * 64;
                const uint32_t rsOff = sub ? RS1_OFF : RS0_OFF;
                float rf[2][4][4];
#pragma unroll
                for (int m = 0; m < 2; m++)
#pragma unroll
                    for (int n = 0; n < 4; n++)
#pragma unroll
                        for (int e = 0; e < 4; e++) rf[m][n][e] = 0.f;
                const uint32_t bB = sb + SA_OFF + (sub * 64 + wc * 32) * 272 + loff272;
                uint32_t a[2][4], b[2][4];
#pragma unroll
                for (int kk = 0; kk < 8; kk++) {
                    ldsm4(a[0], haA + kk * 32);
                    ldsm4(a[1], haA + 16 * 272 + kk * 32);
                    ldsm4(b[0], bB + kk * 32);
                    ldsm4(b[1], bB + 16 * 272 + kk * 32);
#pragma unroll
                    for (int m = 0; m < 2; m++)
#pragma unroll
                        for (int n = 0; n < 4; n++)
                            mma16816(rf[m][n], a[m], b[n >> 1][n & 1], b[n >> 1][(n & 1) + 2]);
                }
                // bias + relu + pack to rS(sub)
#pragma unroll
                for (int m = 0; m < 2; m++)
#pragma unroll
                    for (int n = 0; n < 4; n++) {
                        int c = wc * 32 + n * 8 + (lane & 3) * 2;
                        float2 bias = __ldg((const float2*)(b1s + fsub + c));
                        int rowb = r0 + m * 16 + (lane >> 2);
                        __half2 p0 = __floats2half2_rn(fmaxf(rf[m][n][0] + bias.x, 0.f),
                                                       fmaxf(rf[m][n][1] + bias.y, 0.f));
                        *(uint32_t*)(smem + rsOff + rowb * 144 + c * 2) = *(uint32_t*)&p0;
                        __half2 p1 = __floats2half2_rn(fmaxf(rf[m][n][2] + bias.x, 0.f),
                                                       fmaxf(rf[m][n][3] + bias.y, 0.f));
                        *(uint32_t*)(smem + rsOff + (rowb + 8) * 144 + c * 2) = *(uint32_t*)&p1;
                    }
            }

            cp_wait<0>();
            __syncthreads();   // Wb(it) visible; rS ready; SA reads done

            if (it + 1 < 16) {   // Wa(it+1) -> SA
                const __half* srcA = Wa + (size_t)(f0 + 128) * 128;
                for (int i = tid; i < 2048; i += 512) {
                    int r = i >> 4, q = i & 15;
                    cp16h(sb + SA_OFF + r * 272 + q * 16, srcA + (size_t)r * 128 + q * 8);
                }
            }
            cp_commit();

            // stage 2, sub 0 and 1
#pragma unroll
            for (int sub = 0; sub < 2; sub++) {
                const uint32_t aB = sb + (sub ? RS1_OFF : RS0_OFF) + r0 * 144 + loff144;
                const uint32_t bB = sb + SB_OFF + sub * 18432 + (wc * 64) * 144 + loff144;
                uint32_t a[2][4], b[4][4];
#pragma unroll
                for (int kk = 0; kk < 4; kk++) {
                    ldsm4(a[0], aB + kk * 32);
                    ldsm4(a[1], aB + 16 * 144 + kk * 32);
#pragma unroll
                    for (int g = 0; g < 4; g++) ldsm4(b[g], bB + g * 16 * 144 + kk * 32);
#pragma unroll
                    for (int m = 0; m < 2; m++)
#pragma unroll
                        for (int n = 0; n < 8; n++)
                            mma16816(acc[m][n], a[m], b[n >> 1][n & 1], b[n >> 1][(n & 1) + 2]);
                }
            }
        }

        // ======== FFN epilogue: LN2 -> g_hh (s<2) / z-head (s==2) ========
#pragma unroll
        for (int m = 0; m < 2; m++)
#pragma unroll
            for (int h = 0; h < 2; h++) {
                int lr = r0 + m * 16 + (lane >> 2) + h * 8;
                int gr = row0 + lr;
                float ss = 0.f, qq = 0.f;
                if (gr < N) {
#pragma unroll
                    for (int n = 0; n < 8; n++) {
                        int c = wc * 64 + n * 8 + (lane & 3) * 2;
                        __half2 hh = *(__half2*)(smem + HA_OFF + lr * 272 + c * 2);
                        float2 ho = __half22float2(hh);
                        float v0 = acc[m][n][h * 2 + 0] + ho.x + bb2S[c];
                        float v1 = acc[m][n][h * 2 + 1] + ho.y + bb2S[c + 1];
                        ss += v0 + v1;
                        qq += v0 * v0 + v1 * v1;
                    }
                }
                ss += __shfl_xor_sync(0xffffffffu, ss, 1);
                ss += __shfl_xor_sync(0xffffffffu, ss, 2);
                qq += __shfl_xor_sync(0xffffffffu, qq, 1);
                qq += __shfl_xor_sync(0xffffffffu, qq, 2);
                if ((lane & 3) == 0) red[lr * 2 + wc] = make_float2(ss, qq);
            }
        asm volatile("bar.sync %0, 64;" :: "r"(1 + wr) : "memory");
#pragma unroll
        for (int m = 0; m < 2; m++)
#pragma unroll
            for (int h = 0; h < 2; h++) {
                int lr = r0 + m * 16 + (lane >> 2) + h * 8;
                int gr = row0 + lr;
                float zp = 0.f;
                if (gr < N) {
                    float2 p0 = red[lr * 2 + 0], p1 = red[lr * 2 + 1];
                    float mean = (p0.x + p1.x) * (1.f / 128.f);
                    float inv = rsqrtf((p0.y + p1.y) * (1.f / 128.f) - mean * mean + 1e-5f);
#pragma unroll
                    for (int n = 0; n < 8; n++) {
                        int c = wc * 64 + n * 8 + (lane & 3) * 2;
                        __half2 hh = *(__half2*)(smem + HA_OFF + lr * 272 + c * 2);
                        float2 ho = __half22float2(hh);
                        float v0 = acc[m][n][h * 2 + 0] + ho.x + bb2S[c];
                        float v1 = acc[m][n][h * 2 + 1] + ho.y + bb2S[c + 1];
                        float o0 = (v0 - mean) * inv * lng2S[c] + lnb2S[c];
                        float o1 = (v1 - mean) * inv * lng2S[c + 1] + lnb2S[c + 1];
                        if (s != 2) {
                            *(__half2*)(g_hh + (size_t)gr * D + c) = __floats2half2_rn(o0, o1);
                        } else {
                            zp += o0 * WdS[c] + o1 * WdS[c + 1];
                        }
                    }
                }
                if (s == 2) {
                    zp += __shfl_xor_sync(0xffffffffu, zp, 1);
                    zp += __shfl_xor_sync(0xffffffffu, zp, 2);
                    if ((lane & 3) == 0) zred[lr * 2 + wc] = zp;
                }
            }
        if (s == 2) {
            asm volatile("bar.sync %0, 64;" :: "r"(1 + wr) : "memory");
#pragma unroll
            for (int m = 0; m < 2; m++)
#pragma unroll
                for (int h = 0; h < 2; h++) {
                    int lr = r0 + m * 16 + (lane >> 2) + h * 8;
                    int gr = row0 + lr;
                    if (gr < N && (lane & 3) == 0 && wc == 0)
                        g_z[gr] = fmaxf(zred[lr * 2] + zred[lr * 2 + 1] + WdS[128], 0.f);
                }
        }

        __threadfence();
        __syncthreads();
        if (tid == 0 && s < 2) atomicExch(&g_done[s * ntiles + t], 1);
    }
}

// ---------------------------------------------------------------------------
__global__ void k_dis_u(int N) {
    int n = blockIdx.x * blockDim.x + threadIdx.x;
    if (n >= N) return;
    float dis = rsqrtf(fmaxf(g_deg[n], 1.0f));
    float u = g_z[n] * dis;
    g_dis[n] = dis;
    g_u[n] = u;
    g_t[n] = u;
}
__global__ void k_scatter(const int* __restrict__ row, const int* __restrict__ col, int E) {
    int e = blockIdx.x * blockDim.x + threadIdx.x;
    if (e < E) atomicAdd(&g_t[col[e]], g_u[row[e]]);
}
__global__ void k_out(const float* __restrict__ Wg, const float* __restrict__ bg,
                      const float* __restrict__ Wf, const float* __restrict__ bf,
                      float* __restrict__ out, int N) {
    int n = blockIdx.x * blockDim.x + threadIdx.x;
    if (n >= N) return;
    float s = g_dis[n] * g_t[n];
    float a = bf[0];
#pragma unroll
    for (int k = 0; k < 32; k++)
        a += fmaxf(s * Wg[k] + bg[k], 0.f) * Wf[k];
    out[n] = a;
}

// ---------------------------------------------------------------------------
extern "C" void kernel_launch(void* const* d_in, const int* in_sizes, int n_in,
                              void* d_out, int out_size) {
    const float* x    = (const float*)d_in[0];
    const int*   edge = (const int*)  d_in[1];
    const float* Win  = (const float*)d_in[2];
    const float* b_in = (const float*)d_in[3];
    const float* Wv   = (const float*)d_in[4];
    const float* bv   = (const float*)d_in[5];
    const float* Wo   = (const float*)d_in[6];
    const float* bo   = (const float*)d_in[7];
    const float* W1   = (const float*)d_in[8];
    const float* b1   = (const float*)d_in[9];
    const float* W2   = (const float*)d_in[10];
    const float* b2   = (const float*)d_in[11];
    const float* ln1g = (const float*)d_in[12];
    const float* ln1b = (const float*)d_in[13];
    const float* ln2g = (const float*)d_in[14];
    const float* ln2b = (const float*)d_in[15];
    const float* Wd   = (const float*)d_in[16];
    const float* bd   = (const float*)d_in[17];
    const float* Wg   = (const float*)d_in[18];
    const float* bg   = (const float*)d_in[19];
    const float* Wf   = (const float*)d_in[20];
    const float* bf   = (const float*)d_in[21];

    const int N = in_sizes[0] / 3;
    const int E = in_sizes[1] / 2;
    const int ntiles = (N + BR - 1) / BR;
    const int degblocks = (N + 255) / 256;

    int sms = 148;
    cudaDeviceGetAttribute(&sms, cudaDevAttrMultiProcessorCount, 0);

    cudaFuncSetAttribute(mega, cudaFuncAttributeMaxDynamicSharedMemorySize, SMEM_BYTES);

    k_prep<<<6576 + degblocks + 1, 256>>>(W1, W2, Wo, Wv, bv, bo, N, degblocks);

    mega<<<sms, 512, SMEM_BYTES>>>(x, Win, b_in, b1, b2, ln1g, ln1b, ln2g, ln2b,
                                   Wd, bd, edge + E, E, N, ntiles);

    k_dis_u<<<(N + 255) / 256, 256>>>(N);
    k_scatter<<<(E + 255) / 256, 256>>>(edge, edge + E, E);
    k_out<<<(N + 255) / 256, 256>>>(Wg, bg, Wf, bf, (float*)d_out, N);
}